// round 8
// baseline (speedup 1.0000x reference)
#include <cuda_runtime.h>

#define NTH 256
#define L2E2 2.8853900817779268f   // 2*log2(e)

__device__ float g_partial[1024];
__device__ unsigned int g_count = 0;

__device__ __forceinline__ float ex2f(float x){float r;asm("ex2.approx.f32 %0,%1;":"=f"(r):"f"(x));return r;}
__device__ __forceinline__ float rcpf(float x){float r;asm("rcp.approx.f32 %0,%1;":"=f"(r):"f"(x));return r;}
// tanh with input pre-scaled by 2*log2(e): tanh = 1 - 2/(2^t + 1)
__device__ __forceinline__ float tanh_pre(float t){
    return fmaf(-2.f, rcpf(ex2f(t) + 1.f), 1.f);
}
__device__ __forceinline__ float ent_term(float w){
    w = fminf(fmaxf(w, 1e-12f), 1.0f);
    return -w * __logf(w);
}

struct __align__(16) SW {
    float W1s[2][16];    // prescaled by L2E2
    float b1s[16];       // prescaled
    float W2s[16][4];
    float b2s[4];
    float coef[26][16];  // quadratic-form rows; [0..15] prescaled by L2E2; entry 15 = pad 0
    float b3s[16];       // prescaled
    float W4s[16][2];
    float b4s[2];
    // staging scratch (live only between the two syncthreads)
    float wr5[20][5];    // (Wr[j][k]+Wr[j+4][k] for j<4, br[k])
    float wi5[20][5];
    float W3s[20][16];
};

// dot of 14 monomials + constant term (coef[14]); coef[15] is pad
__device__ __forceinline__ float dot16(const float* cf, const float4* yv){
    const float4* c4 = (const float4*)cf;
    float4 c0 = c4[0], c1 = c4[1], c2 = c4[2], c3 = c4[3];
    float4 y0 = yv[0], y1 = yv[1], y2 = yv[2], y3 = yv[3];
    float a = c3.z;                   // constant-term coefficient (monomial "1")
    float b2_ = 0.f;
    a   = fmaf(c0.x, y0.x, a);   b2_ = fmaf(c0.y, y0.y, b2_);
    a   = fmaf(c0.z, y0.z, a);   b2_ = fmaf(c0.w, y0.w, b2_);
    a   = fmaf(c1.x, y1.x, a);   b2_ = fmaf(c1.y, y1.y, b2_);
    a   = fmaf(c1.z, y1.z, a);   b2_ = fmaf(c1.w, y1.w, b2_);
    a   = fmaf(c2.x, y2.x, a);   b2_ = fmaf(c2.y, y2.y, b2_);
    a   = fmaf(c2.z, y2.z, a);   b2_ = fmaf(c2.w, y2.w, b2_);
    a   = fmaf(c3.x, y3.x, a);   b2_ = fmaf(c3.y, y3.y, b2_);
    return a + b2_;
}

__global__ __launch_bounds__(NTH, 4) void qpinn_fused(
    const float* __restrict__ xt,
    const float* __restrict__ W1, const float* __restrict__ b1,
    const float* __restrict__ W2, const float* __restrict__ b2,
    const float* __restrict__ Wr, const float* __restrict__ br,
    const float* __restrict__ Wi, const float* __restrict__ bi,
    const float* __restrict__ W3, const float* __restrict__ b3,
    const float* __restrict__ W4, const float* __restrict__ b4,
    float* __restrict__ out, int n)
{
    __shared__ SW s;
    __shared__ float red[NTH / 32];
    __shared__ bool s_last;
    const int tid = threadIdx.x;

    // ---- phase A: stage raw weights ----
    if (tid < 32) ((float*)s.W1s)[tid] = W1[tid] * L2E2;
    if (tid < 16) s.b1s[tid] = b1[tid] * L2E2;
    if (tid < 64) ((float*)s.W2s)[tid] = W2[tid];
    if (tid < 4)  s.b2s[tid] = b2[tid];
    if (tid < 16) s.b3s[tid] = b3[tid] * L2E2;
    if (tid < 32) ((float*)s.W4s)[tid] = W4[tid];
    if (tid < 2)  s.b4s[tid] = b4[tid];
    if (tid < 100) {
        int k = tid / 5, i = tid % 5;
        s.wr5[k][i] = (i < 4) ? (Wr[i*20 + k] + Wr[(i+4)*20 + k]) : br[k];
        s.wi5[k][i] = (i < 4) ? (Wi[i*20 + k] + Wi[(i+4)*20 + k]) : bi[k];
    }
    ((float*)s.W3s)[tid] = W3[tid];
    if (tid < 64) ((float*)s.W3s)[256 + tid] = W3[256 + tid];
    __syncthreads();

    // ---- phase B: build 26 quadratic-form coefficient rows (once per block) ----
    {
        const int EI[15] = {0,0,0,0,0,1,1,1,1,2,2,2,3,3,4};
        const int EJ[15] = {0,1,2,3,4,1,2,3,4,2,3,4,3,4,4};
        for (int v = tid; v < 26*16; v += NTH) {
            int f = v >> 4, e = v & 15;
            float c = 0.f;
            if (e < 15) {
                int i = EI[e], j = EJ[e];
                if (f < 16) {
                    // acc_f = sum_k W3[k][f] * m_k
                    float ssum = 0.f;
                    for (int k = 0; k < 20; k++)
                        ssum += s.W3s[k][f] * (s.wr5[k][i]*s.wr5[k][j] + s.wi5[k][i]*s.wi5[k][j]);
                    if (i != j) ssum *= 2.f;
                    c = ssum * L2E2;
                } else if (f < 22) {
                    // sector sums: sum0, p1m, r1m, p2m, r2m, sum3
                    const signed char SS[6][4] = {
                        {0,1,2,3},{4,5,6,-1},{10,11,12,-1},{7,13,16,-1},{8,14,17,-1},{9,15,18,19}};
                    float ssum = 0.f;
                    for (int t = 0; t < 4; t++) {
                        int k = SS[f-16][t];
                        if (k >= 0)
                            ssum += s.wr5[k][i]*s.wr5[k][j] + s.wi5[k][i]*s.wi5[k][j];
                    }
                    if (i != j) ssum *= 2.f;
                    c = ssum;
                } else {
                    // bilinear cross terms: f=22 c1r, 23 c1i, 24 c2r, 25 c2i
                    const signed char PA[4][3] = {{4,5,6},{4,5,6},{7,13,16},{7,13,16}};
                    const signed char PB[4][3] = {{10,11,12},{10,11,12},{8,14,17},{8,14,17}};
                    bool isR = (((f - 22) & 1) == 0);
                    float ssum = 0.f;
                    for (int t = 0; t < 3; t++) {
                        int ka = PA[f-22][t], kb = PB[f-22][t];
                        const float* ra = s.wr5[ka]; const float* rb = s.wr5[kb];
                        const float* ia = s.wi5[ka]; const float* ib = s.wi5[kb];
                        float srr = (i == j) ? ra[i]*rb[i] : ra[i]*rb[j] + ra[j]*rb[i];
                        float sii = (i == j) ? ia[i]*ib[i] : ia[i]*ib[j] + ia[j]*ib[i];
                        float sir = (i == j) ? ia[i]*rb[i] : ia[i]*rb[j] + ia[j]*rb[i];
                        float sri = (i == j) ? ra[i]*ib[i] : ra[i]*ib[j] + ra[j]*ib[i];
                        ssum += isR ? (srr + sii) : (sir - sri);
                    }
                    c = ssum;
                }
            }
            s.coef[f][e] = c;
        }
    }
    __syncthreads();

    const int b = blockIdx.x * NTH + tid;
    const float2 x = reinterpret_cast<const float2*>(xt)[b];

    // ---- layer 1 (2->16, tanh, prescaled) fused into layer 2 (16->4) ----
    float4 z = *reinterpret_cast<const float4*>(s.b2s);
    {
        const float4* wa = reinterpret_cast<const float4*>(s.W1s[0]);
        const float4* wb = reinterpret_cast<const float4*>(s.W1s[1]);
        const float4* bv = reinterpret_cast<const float4*>(s.b1s);
        const float4* w2 = reinterpret_cast<const float4*>(s.W2s);
        #pragma unroll
        for (int i = 0; i < 4; i++) {
            float4 a = wa[i], c = wb[i], bb = bv[i];
            float h0 = tanh_pre(fmaf(x.x, a.x, fmaf(x.y, c.x, bb.x)));
            float h1 = tanh_pre(fmaf(x.x, a.y, fmaf(x.y, c.y, bb.y)));
            float h2 = tanh_pre(fmaf(x.x, a.z, fmaf(x.y, c.z, bb.z)));
            float h3 = tanh_pre(fmaf(x.x, a.w, fmaf(x.y, c.w, bb.w)));
            float4 q0 = w2[4*i], q1 = w2[4*i+1], q2 = w2[4*i+2], q3 = w2[4*i+3];
            z.x = fmaf(h0, q0.x, fmaf(h1, q1.x, fmaf(h2, q2.x, fmaf(h3, q3.x, z.x))));
            z.y = fmaf(h0, q0.y, fmaf(h1, q1.y, fmaf(h2, q2.y, fmaf(h3, q3.y, z.y))));
            z.z = fmaf(h0, q0.z, fmaf(h1, q1.z, fmaf(h2, q2.z, fmaf(h3, q3.z, z.z))));
            z.w = fmaf(h0, q0.w, fmaf(h1, q1.w, fmaf(h2, q2.w, fmaf(h3, q3.w, z.w))));
        }
    }

    // ---- monomials of v = (z, 1): order matches EI/EJ ----
    float4 yv[4];
    yv[0] = make_float4(z.x*z.x, z.x*z.y, z.x*z.z, z.x*z.w);
    yv[1] = make_float4(z.x,     z.y*z.y, z.y*z.z, z.y*z.w);
    yv[2] = make_float4(z.y,     z.z*z.z, z.z*z.w, z.z);
    yv[3] = make_float4(z.w*z.w, z.w,     0.f,     0.f);

    // ---- entropy: 10 quadratic forms -> closed-form sector eigenvalues ----
    float sum0 = dot16(s.coef[16], yv);
    float p1m  = dot16(s.coef[17], yv);
    float r1m  = dot16(s.coef[18], yv);
    float p2m  = dot16(s.coef[19], yv);
    float r2m  = dot16(s.coef[20], yv);
    float sum3 = dot16(s.coef[21], yv);
    float c1r  = dot16(s.coef[22], yv);
    float c1i  = dot16(s.coef[23], yv);
    float c2r  = dot16(s.coef[24], yv);
    float c2i  = dot16(s.coef[25], yv);

    const float n2 = sum0 + sum3 + p1m + r1m + p2m + r2m;
    const float inv2 = __frcp_rn(n2);
    const float invsq = inv2 * inv2;

    float s0 = sum0 * inv2, s3 = sum3 * inv2;
    float p1 = p1m * inv2, r1 = r1m * inv2;
    float c1s = fmaf(c1r, c1r, c1i * c1i) * invsq;
    float t1 = p1 - r1;
    float d1 = sqrtf(fmaf(t1, t1, 4.f * c1s));
    float l1a = 0.5f * ((p1 + r1) + d1);
    float l1b = 0.5f * ((p1 + r1) - d1);
    float p2 = p2m * inv2, r2 = r2m * inv2;
    float c2s = fmaf(c2r, c2r, c2i * c2i) * invsq;
    float t2 = p2 - r2;
    float d2 = sqrtf(fmaf(t2, t2, 4.f * c2s));
    float l2a = 0.5f * ((p2 + r2) + d2);
    float l2b = 0.5f * ((p2 + r2) - d2);
    float e = ent_term(s0) + ent_term(l1a) + ent_term(l1b)
            + ent_term(l2a) + ent_term(l2b) + ent_term(s3)
            + 1.1052408e-10f;   // 4 zero-eigs clipped to 1e-12 in reference

    // ---- layers 3+4: acc form -> tanh -> W4, one j at a time (no acc array) ----
    float o0 = s.b4s[0], o1 = s.b4s[1];
    #pragma unroll
    for (int j = 0; j < 16; j++) {
        float t = fmaf(inv2, dot16(s.coef[j], yv), s.b3s[j]);
        float g = tanh_pre(t);
        float2 w = *reinterpret_cast<const float2*>(s.W4s[j]);
        o0 = fmaf(g, w.x, o0);
        o1 = fmaf(g, w.y, o1);
    }

    out[b]     = x.x * (1.0f - x.x) * o0;
    out[n + b] = o1;

    // ---- deterministic entropy partial sum + fused final mean ----
    #pragma unroll
    for (int o = 16; o > 0; o >>= 1) e += __shfl_xor_sync(0xffffffffu, e, o);
    if ((tid & 31) == 0) red[tid >> 5] = e;
    __syncthreads();
    if (tid == 0) {
        float ssum = 0.f;
        #pragma unroll
        for (int i = 0; i < NTH / 32; i++) ssum += red[i];
        g_partial[blockIdx.x] = ssum;
        __threadfence();
        unsigned old = atomicAdd(&g_count, 1u);
        s_last = (old == gridDim.x - 1);
    }
    __syncthreads();
    if (s_last) {
        const int nblk = gridDim.x;
        float v = 0.f;
        for (int i = tid; i < nblk; i += NTH) v += g_partial[i];
        #pragma unroll
        for (int o = 16; o > 0; o >>= 1) v += __shfl_xor_sync(0xffffffffu, v, o);
        if ((tid & 31) == 0) red[tid >> 5] = v;
        __syncthreads();
        if (tid == 0) {
            float sum = 0.f;
            #pragma unroll
            for (int i = 0; i < NTH / 32; i++) sum += red[i];
            out[2 * n] = sum / (float)n;
            g_count = 0;   // reset for next graph replay
        }
    }
}

extern "C" void kernel_launch(void* const* d_in, const int* in_sizes, int n_in,
                              void* d_out, int out_size)
{
    const float* xt = (const float*)d_in[0];
    const float* W1 = (const float*)d_in[1];
    const float* b1 = (const float*)d_in[2];
    const float* W2 = (const float*)d_in[3];
    const float* b2 = (const float*)d_in[4];
    const float* Wr = (const float*)d_in[5];
    const float* br = (const float*)d_in[6];
    const float* Wi = (const float*)d_in[7];
    const float* bi = (const float*)d_in[8];
    const float* W3 = (const float*)d_in[9];
    const float* b3 = (const float*)d_in[10];
    const float* W4 = (const float*)d_in[11];
    const float* b4 = (const float*)d_in[12];
    // d_in[13] = state_map: fixed 3-photon/4-mode basis, structure hardcoded

    const int n    = in_sizes[0] / 2;
    const int nblk = n / NTH;   // 512

    float* out = (float*)d_out;
    qpinn_fused<<<nblk, NTH>>>(xt, W1, b1, W2, b2, Wr, br, Wi, bi,
                               W3, b3, W4, b4, out, n);
}

// round 9
// speedup vs baseline: 1.2521x; 1.2521x over previous
#include <cuda_runtime.h>

#define NTH 128
#define L2E2 2.8853900817779268f   // 2*log2(e)

__device__ float g_partial[1024];
__device__ unsigned int g_count = 0;

__device__ __forceinline__ float ex2f(float x){float r;asm("ex2.approx.f32 %0,%1;":"=f"(r):"f"(x));return r;}
__device__ __forceinline__ float rcpf(float x){float r;asm("rcp.approx.f32 %0,%1;":"=f"(r):"f"(x));return r;}
// tanh with argument pre-scaled by 2*log2(e): tanh = 1 - 2/(2^t + 1)
__device__ __forceinline__ float tanh_pre(float t){
    return fmaf(-2.f, rcpf(ex2f(t) + 1.f), 1.f);
}
__device__ __forceinline__ float ent_term(float w){
    w = fminf(fmaxf(w, 1e-12f), 1.0f);
    return -w * __logf(w);
}

struct __align__(16) SW {
    float W1[2][16];      // prescaled by L2E2
    float b1[16];         // prescaled
    float W2[16][4];
    float b2[4];
    float Wrct[20][4];    // Wr[j,k]+Wr[j+4,k] (z_re dup folded), transposed [k][j]
    float Wict[20][4];
    float2 brbi[20];      // (br[k], bi[k])
    float W3[20][16];     // prescaled by L2E2
    float b3[16];         // prescaled
    float W4[16][2];
    float b4[4];
};

__global__ __launch_bounds__(NTH, 8) void qpinn_fused(
    const float* __restrict__ xt,
    const float* __restrict__ W1, const float* __restrict__ b1,
    const float* __restrict__ W2, const float* __restrict__ b2,
    const float* __restrict__ Wr, const float* __restrict__ br,
    const float* __restrict__ Wi, const float* __restrict__ bi,
    const float* __restrict__ W3, const float* __restrict__ b3,
    const float* __restrict__ W4, const float* __restrict__ b4,
    float* __restrict__ out, int n)
{
    __shared__ SW s;
    __shared__ float red[NTH / 32];
    __shared__ bool s_last;
    const int tid = threadIdx.x;

    // ---- cooperative weight staging ----
    if (tid < 32) ((float*)s.W1)[tid] = W1[tid] * L2E2;
    if (tid < 16) s.b1[tid] = b1[tid] * L2E2;
    if (tid < 64) ((float*)s.W2)[tid] = W2[tid];
    if (tid < 4)  s.b2[tid] = b2[tid];
    if (tid < 80) {
        int j = tid & 3, k = tid >> 2;
        s.Wrct[k][j] = Wr[j*20 + k] + Wr[(j+4)*20 + k];
        s.Wict[k][j] = Wi[j*20 + k] + Wi[(j+4)*20 + k];
    }
    if (tid < 20) s.brbi[tid] = make_float2(br[tid], bi[tid]);
    #pragma unroll
    for (int i = tid; i < 320; i += NTH) ((float*)s.W3)[i] = W3[i] * L2E2;
    if (tid < 16) s.b3[tid] = b3[tid] * L2E2;
    if (tid < 32) ((float*)s.W4)[tid] = W4[tid];
    if (tid < 2)  s.b4[tid] = b4[tid];
    __syncthreads();

    const int b = blockIdx.x * NTH + tid;
    const float2 x = reinterpret_cast<const float2*>(xt)[b];

    // ---- layer 1 (2->16, tanh, prescaled) fused into layer 2 (16->4) ----
    float4 z = *reinterpret_cast<const float4*>(s.b2);
    {
        const float4* wa = reinterpret_cast<const float4*>(s.W1[0]);
        const float4* wb = reinterpret_cast<const float4*>(s.W1[1]);
        const float4* bv = reinterpret_cast<const float4*>(s.b1);
        const float4* w2 = reinterpret_cast<const float4*>(s.W2);
        #pragma unroll
        for (int i = 0; i < 4; i++) {
            float4 a = wa[i], c = wb[i], bb = bv[i];
            float h0 = tanh_pre(fmaf(x.x, a.x, fmaf(x.y, c.x, bb.x)));
            float h1 = tanh_pre(fmaf(x.x, a.y, fmaf(x.y, c.y, bb.y)));
            float h2 = tanh_pre(fmaf(x.x, a.z, fmaf(x.y, c.z, bb.z)));
            float h3 = tanh_pre(fmaf(x.x, a.w, fmaf(x.y, c.w, bb.w)));
            float4 q0 = w2[4*i], q1 = w2[4*i+1], q2 = w2[4*i+2], q3 = w2[4*i+3];
            z.x = fmaf(h0, q0.x, fmaf(h1, q1.x, fmaf(h2, q2.x, fmaf(h3, q3.x, z.x))));
            z.y = fmaf(h0, q0.y, fmaf(h1, q1.y, fmaf(h2, q2.y, fmaf(h3, q3.y, z.y))));
            z.z = fmaf(h0, q0.z, fmaf(h1, q1.z, fmaf(h2, q2.z, fmaf(h3, q3.z, z.z))));
            z.w = fmaf(h0, q0.w, fmaf(h1, q1.w, fmaf(h2, q2.w, fmaf(h3, q3.w, z.w))));
        }
    }

    // ---- amplitudes + |.|^2 streamed into layer-3 accumulators + entropy sums ----
    float acc[16];
    #pragma unroll
    for (int j = 0; j < 16; j++) acc[j] = 0.f;

    #define AMPK(k, re, im) do { \
        float4 wr_ = *reinterpret_cast<const float4*>(s.Wrct[k]); \
        float4 wi_ = *reinterpret_cast<const float4*>(s.Wict[k]); \
        float2 bb_ = s.brbi[k]; \
        re = fmaf(z.x, wr_.x, fmaf(z.y, wr_.y, fmaf(z.z, wr_.z, fmaf(z.w, wr_.w, bb_.x)))); \
        im = fmaf(z.x, wi_.x, fmaf(z.y, wi_.y, fmaf(z.z, wi_.z, fmaf(z.w, wi_.w, bb_.y)))); \
    } while (0)
    #define ACC3(k, mm) do { \
        const float4* w_ = reinterpret_cast<const float4*>(s.W3[k]); \
        float4 w0 = w_[0], w1 = w_[1], w2_ = w_[2], w3_ = w_[3]; \
        acc[0]  = fmaf(mm, w0.x, acc[0]);  acc[1]  = fmaf(mm, w0.y, acc[1]); \
        acc[2]  = fmaf(mm, w0.z, acc[2]);  acc[3]  = fmaf(mm, w0.w, acc[3]); \
        acc[4]  = fmaf(mm, w1.x, acc[4]);  acc[5]  = fmaf(mm, w1.y, acc[5]); \
        acc[6]  = fmaf(mm, w1.z, acc[6]);  acc[7]  = fmaf(mm, w1.w, acc[7]); \
        acc[8]  = fmaf(mm, w2_.x, acc[8]); acc[9]  = fmaf(mm, w2_.y, acc[9]); \
        acc[10] = fmaf(mm, w2_.z, acc[10]); acc[11] = fmaf(mm, w2_.w, acc[11]); \
        acc[12] = fmaf(mm, w3_.x, acc[12]); acc[13] = fmaf(mm, w3_.y, acc[13]); \
        acc[14] = fmaf(mm, w3_.z, acc[14]); acc[15] = fmaf(mm, w3_.w, acc[15]); \
    } while (0)

    float sum0 = 0.f, sum3 = 0.f;
    float p1m = 0.f, r1m = 0.f, c1r = 0.f, c1i = 0.f;
    float p2m = 0.f, r2m = 0.f, c2r = 0.f, c2i = 0.f;

    {   // sector n_A=0: states 0..3 (1x1 block)
        #pragma unroll
        for (int k = 0; k < 4; k++) {
            float re, im; AMPK(k, re, im);
            float mm = fmaf(re, re, im * im);
            sum0 += mm; ACC3(k, mm);
        }
    }
    {   // sector n_A=1: pairs (4,10),(5,11),(6,12) -> 2x2 Hermitian
        const int ka[3] = {4, 5, 6}, kb[3] = {10, 11, 12};
        #pragma unroll
        for (int t = 0; t < 3; t++) {
            float rea, ima, reb, imb;
            AMPK(ka[t], rea, ima); AMPK(kb[t], reb, imb);
            float ma = fmaf(rea, rea, ima * ima);
            float mb = fmaf(reb, reb, imb * imb);
            p1m += ma; r1m += mb;
            c1r = fmaf(rea, reb, fmaf(ima, imb, c1r));
            c1i = fmaf(ima, reb, fmaf(-rea, imb, c1i));   // only |c|^2 used
            ACC3(ka[t], ma); ACC3(kb[t], mb);
        }
    }
    {   // sector n_A=2: pairs (7,8),(13,14),(16,17) -> 2x2 Hermitian
        const int ka[3] = {7, 13, 16}, kb[3] = {8, 14, 17};
        #pragma unroll
        for (int t = 0; t < 3; t++) {
            float rea, ima, reb, imb;
            AMPK(ka[t], rea, ima); AMPK(kb[t], reb, imb);
            float ma = fmaf(rea, rea, ima * ima);
            float mb = fmaf(reb, reb, imb * imb);
            p2m += ma; r2m += mb;
            c2r = fmaf(rea, reb, fmaf(ima, imb, c2r));
            c2i = fmaf(ima, reb, fmaf(-rea, imb, c2i));
            ACC3(ka[t], ma); ACC3(kb[t], mb);
        }
    }
    {   // sector n_A=3: states 9,15,18,19 (rank-1)
        const int ks[4] = {9, 15, 18, 19};
        #pragma unroll
        for (int t = 0; t < 4; t++) {
            float re, im; AMPK(ks[t], re, im);
            float mm = fmaf(re, re, im * im);
            sum3 += mm; ACC3(ks[t], mm);
        }
    }
    #undef AMPK
    #undef ACC3

    const float n2 = sum0 + sum3 + p1m + r1m + p2m + r2m;
    const float inv2 = __frcp_rn(n2);
    const float invsq = inv2 * inv2;

    // ---- entropy from closed-form sector eigenvalues ----
    float s0 = sum0 * inv2, s3 = sum3 * inv2;
    float p1 = p1m * inv2, r1 = r1m * inv2;
    float c1s = fmaf(c1r, c1r, c1i * c1i) * invsq;
    float t1 = p1 - r1;
    float d1 = sqrtf(fmaf(t1, t1, 4.f * c1s));
    float l1a = 0.5f * ((p1 + r1) + d1);
    float l1b = 0.5f * ((p1 + r1) - d1);
    float p2 = p2m * inv2, r2 = r2m * inv2;
    float c2s = fmaf(c2r, c2r, c2i * c2i) * invsq;
    float t2 = p2 - r2;
    float d2 = sqrtf(fmaf(t2, t2, 4.f * c2s));
    float l2a = 0.5f * ((p2 + r2) + d2);
    float l2b = 0.5f * ((p2 + r2) - d2);
    float e = ent_term(s0) + ent_term(l1a) + ent_term(l1b)
            + ent_term(l2a) + ent_term(l2b) + ent_term(s3)
            + 1.1052408e-10f;   // 4 zero-eigs clipped to 1e-12 in the reference

    // ---- layer 3 epilogue (prescaled tanh) + layer 4 (16->2) ----
    float o0 = s.b4[0], o1 = s.b4[1];
    #pragma unroll
    for (int j = 0; j < 16; j++) {
        float g = tanh_pre(fmaf(inv2, acc[j], s.b3[j]));
        float2 w = *reinterpret_cast<const float2*>(s.W4[j]);
        o0 = fmaf(g, w.x, o0);
        o1 = fmaf(g, w.y, o1);
    }

    out[b]     = x.x * (1.0f - x.x) * o0;
    out[n + b] = o1;

    // ---- deterministic entropy partial sum + fused final mean ----
    #pragma unroll
    for (int o = 16; o > 0; o >>= 1) e += __shfl_xor_sync(0xffffffffu, e, o);
    if ((tid & 31) == 0) red[tid >> 5] = e;
    __syncthreads();
    if (tid == 0) {
        float ssum = 0.f;
        #pragma unroll
        for (int i = 0; i < NTH / 32; i++) ssum += red[i];
        g_partial[blockIdx.x] = ssum;
        __threadfence();
        unsigned old = atomicAdd(&g_count, 1u);
        s_last = (old == gridDim.x - 1);
    }
    __syncthreads();
    if (s_last) {
        const int nblk = gridDim.x;
        float v = 0.f;
        for (int i = tid; i < nblk; i += NTH) v += g_partial[i];
        #pragma unroll
        for (int o = 16; o > 0; o >>= 1) v += __shfl_xor_sync(0xffffffffu, v, o);
        if ((tid & 31) == 0) red[tid >> 5] = v;
        __syncthreads();
        if (tid == 0) {
            float sum = 0.f;
            #pragma unroll
            for (int i = 0; i < NTH / 32; i++) sum += red[i];
            out[2 * n] = sum / (float)n;
            g_count = 0;   // reset for next graph replay
        }
    }
}

extern "C" void kernel_launch(void* const* d_in, const int* in_sizes, int n_in,
                              void* d_out, int out_size)
{
    const float* xt = (const float*)d_in[0];
    const float* W1 = (const float*)d_in[1];
    const float* b1 = (const float*)d_in[2];
    const float* W2 = (const float*)d_in[3];
    const float* b2 = (const float*)d_in[4];
    const float* Wr = (const float*)d_in[5];
    const float* br = (const float*)d_in[6];
    const float* Wi = (const float*)d_in[7];
    const float* bi = (const float*)d_in[8];
    const float* W3 = (const float*)d_in[9];
    const float* b3 = (const float*)d_in[10];
    const float* W4 = (const float*)d_in[11];
    const float* b4 = (const float*)d_in[12];
    // d_in[13] = state_map: fixed 3-photon/4-mode basis, structure hardcoded

    const int n    = in_sizes[0] / 2;
    const int nblk = n / NTH;   // 1024 blocks -> near-perfect wave balance (6.92/SM)

    float* out = (float*)d_out;
    qpinn_fused<<<nblk, NTH>>>(xt, W1, b1, W2, b2, Wr, br, Wi, bi,
                               W3, b3, W4, b4, out, n);
}

// round 10
// speedup vs baseline: 1.3163x; 1.0512x over previous
#include <cuda_runtime.h>

#define NTH 128
#define L2E2 2.8853900817779268f   // 2*log2(e)

__device__ float g_partial[1024];
__device__ unsigned int g_count = 0;

__device__ __forceinline__ float ex2f(float x){float r;asm("ex2.approx.f32 %0,%1;":"=f"(r):"f"(x));return r;}
__device__ __forceinline__ float rcpf(float x){float r;asm("rcp.approx.f32 %0,%1;":"=f"(r):"f"(x));return r;}
// tanh with argument pre-scaled by 2*log2(e): tanh = 1 - 2/(2^t + 1)
__device__ __forceinline__ float tanh_pre(float t){
    return fmaf(-2.f, rcpf(ex2f(t) + 1.f), 1.f);
}
__device__ __forceinline__ float ent_term(float w){
    w = fminf(fmaxf(w, 1e-12f), 1.0f);
    return -w * __logf(w);
}

struct __align__(16) SW {
    float W1[2][16];      // prescaled by L2E2
    float b1[16];         // prescaled
    float W2[16][4];
    float b2[4];
    float Wrct[20][4];    // Wr[j,k]+Wr[j+4,k] (z_re dup folded), transposed [k][j]
    float Wict[20][4];
    float2 brbi[20];      // (br[k], bi[k])
    float W3[20][16];     // prescaled by L2E2
    float b3[16];         // prescaled
    float W4[16][2];
    float b4[4];
};

__global__ __launch_bounds__(NTH, 7) void qpinn_fused(
    const float* __restrict__ xt,
    const float* __restrict__ W1, const float* __restrict__ b1,
    const float* __restrict__ W2, const float* __restrict__ b2,
    const float* __restrict__ Wr, const float* __restrict__ br,
    const float* __restrict__ Wi, const float* __restrict__ bi,
    const float* __restrict__ W3, const float* __restrict__ b3,
    const float* __restrict__ W4, const float* __restrict__ b4,
    float* __restrict__ out, int n)
{
    __shared__ SW s;
    __shared__ float red[NTH / 32];
    __shared__ bool s_last;
    const int tid = threadIdx.x;
    const int b = blockIdx.x * NTH + tid;

    // issue the per-thread input load FIRST: its DRAM latency hides behind staging
    const float2 x = reinterpret_cast<const float2*>(xt)[b];

    // ---- cooperative weight staging ----
    if (tid < 32) ((float*)s.W1)[tid] = W1[tid] * L2E2;
    if (tid < 16) s.b1[tid] = b1[tid] * L2E2;
    if (tid < 64) ((float*)s.W2)[tid] = W2[tid];
    if (tid < 4)  s.b2[tid] = b2[tid];
    if (tid < 80) {
        int j = tid & 3, k = tid >> 2;
        s.Wrct[k][j] = Wr[j*20 + k] + Wr[(j+4)*20 + k];
        s.Wict[k][j] = Wi[j*20 + k] + Wi[(j+4)*20 + k];
    }
    if (tid < 20) s.brbi[tid] = make_float2(br[tid], bi[tid]);
    #pragma unroll
    for (int i = tid; i < 320; i += NTH) ((float*)s.W3)[i] = W3[i] * L2E2;
    if (tid < 16) s.b3[tid] = b3[tid] * L2E2;
    if (tid < 32) ((float*)s.W4)[tid] = W4[tid];
    if (tid < 2)  s.b4[tid] = b4[tid];
    __syncthreads();

    // ---- layer 1 (2->16, tanh, prescaled) fused into layer 2 (16->4) ----
    float4 z = *reinterpret_cast<const float4*>(s.b2);
    {
        const float4* wa = reinterpret_cast<const float4*>(s.W1[0]);
        const float4* wb = reinterpret_cast<const float4*>(s.W1[1]);
        const float4* bv = reinterpret_cast<const float4*>(s.b1);
        const float4* w2 = reinterpret_cast<const float4*>(s.W2);
        #pragma unroll
        for (int i = 0; i < 4; i++) {
            float4 a = wa[i], c = wb[i], bb = bv[i];
            float h0 = tanh_pre(fmaf(x.x, a.x, fmaf(x.y, c.x, bb.x)));
            float h1 = tanh_pre(fmaf(x.x, a.y, fmaf(x.y, c.y, bb.y)));
            float h2 = tanh_pre(fmaf(x.x, a.z, fmaf(x.y, c.z, bb.z)));
            float h3 = tanh_pre(fmaf(x.x, a.w, fmaf(x.y, c.w, bb.w)));
            float4 q0 = w2[4*i], q1 = w2[4*i+1], q2 = w2[4*i+2], q3 = w2[4*i+3];
            z.x = fmaf(h0, q0.x, fmaf(h1, q1.x, fmaf(h2, q2.x, fmaf(h3, q3.x, z.x))));
            z.y = fmaf(h0, q0.y, fmaf(h1, q1.y, fmaf(h2, q2.y, fmaf(h3, q3.y, z.y))));
            z.z = fmaf(h0, q0.z, fmaf(h1, q1.z, fmaf(h2, q2.z, fmaf(h3, q3.z, z.z))));
            z.w = fmaf(h0, q0.w, fmaf(h1, q1.w, fmaf(h2, q2.w, fmaf(h3, q3.w, z.w))));
        }
    }

    // ---- amplitudes + |.|^2 streamed into layer-3 accumulators + entropy sums ----
    float acc[16];
    #pragma unroll
    for (int j = 0; j < 16; j++) acc[j] = 0.f;

    #define AMPK(k, re, im) do { \
        float4 wr_ = *reinterpret_cast<const float4*>(s.Wrct[k]); \
        float4 wi_ = *reinterpret_cast<const float4*>(s.Wict[k]); \
        float2 bb_ = s.brbi[k]; \
        re = fmaf(z.x, wr_.x, fmaf(z.y, wr_.y, fmaf(z.z, wr_.z, fmaf(z.w, wr_.w, bb_.x)))); \
        im = fmaf(z.x, wi_.x, fmaf(z.y, wi_.y, fmaf(z.z, wi_.z, fmaf(z.w, wi_.w, bb_.y)))); \
    } while (0)
    #define ACC3(k, mm) do { \
        const float4* w_ = reinterpret_cast<const float4*>(s.W3[k]); \
        float4 w0 = w_[0], w1 = w_[1], w2_ = w_[2], w3_ = w_[3]; \
        acc[0]  = fmaf(mm, w0.x, acc[0]);  acc[1]  = fmaf(mm, w0.y, acc[1]); \
        acc[2]  = fmaf(mm, w0.z, acc[2]);  acc[3]  = fmaf(mm, w0.w, acc[3]); \
        acc[4]  = fmaf(mm, w1.x, acc[4]);  acc[5]  = fmaf(mm, w1.y, acc[5]); \
        acc[6]  = fmaf(mm, w1.z, acc[6]);  acc[7]  = fmaf(mm, w1.w, acc[7]); \
        acc[8]  = fmaf(mm, w2_.x, acc[8]); acc[9]  = fmaf(mm, w2_.y, acc[9]); \
        acc[10] = fmaf(mm, w2_.z, acc[10]); acc[11] = fmaf(mm, w2_.w, acc[11]); \
        acc[12] = fmaf(mm, w3_.x, acc[12]); acc[13] = fmaf(mm, w3_.y, acc[13]); \
        acc[14] = fmaf(mm, w3_.z, acc[14]); acc[15] = fmaf(mm, w3_.w, acc[15]); \
    } while (0)

    float sum0 = 0.f, sum3 = 0.f;
    float p1m = 0.f, r1m = 0.f, c1r = 0.f, c1i = 0.f;
    float p2m = 0.f, r2m = 0.f, c2r = 0.f, c2i = 0.f;

    {   // sector n_A=0: states 0..3 (1x1 block)
        #pragma unroll
        for (int k = 0; k < 4; k++) {
            float re, im; AMPK(k, re, im);
            float mm = fmaf(re, re, im * im);
            sum0 += mm; ACC3(k, mm);
        }
    }
    {   // sector n_A=1: pairs (4,10),(5,11),(6,12) -> 2x2 Hermitian
        const int ka[3] = {4, 5, 6}, kb[3] = {10, 11, 12};
        #pragma unroll
        for (int t = 0; t < 3; t++) {
            float rea, ima, reb, imb;
            AMPK(ka[t], rea, ima); AMPK(kb[t], reb, imb);
            float ma = fmaf(rea, rea, ima * ima);
            float mb = fmaf(reb, reb, imb * imb);
            p1m += ma; r1m += mb;
            c1r = fmaf(rea, reb, fmaf(ima, imb, c1r));
            c1i = fmaf(ima, reb, fmaf(-rea, imb, c1i));   // only |c|^2 used
            ACC3(ka[t], ma); ACC3(kb[t], mb);
        }
    }
    {   // sector n_A=2: pairs (7,8),(13,14),(16,17) -> 2x2 Hermitian
        const int ka[3] = {7, 13, 16}, kb[3] = {8, 14, 17};
        #pragma unroll
        for (int t = 0; t < 3; t++) {
            float rea, ima, reb, imb;
            AMPK(ka[t], rea, ima); AMPK(kb[t], reb, imb);
            float ma = fmaf(rea, rea, ima * ima);
            float mb = fmaf(reb, reb, imb * imb);
            p2m += ma; r2m += mb;
            c2r = fmaf(rea, reb, fmaf(ima, imb, c2r));
            c2i = fmaf(ima, reb, fmaf(-rea, imb, c2i));
            ACC3(ka[t], ma); ACC3(kb[t], mb);
        }
    }
    {   // sector n_A=3: states 9,15,18,19 (rank-1)
        const int ks[4] = {9, 15, 18, 19};
        #pragma unroll
        for (int t = 0; t < 4; t++) {
            float re, im; AMPK(ks[t], re, im);
            float mm = fmaf(re, re, im * im);
            sum3 += mm; ACC3(ks[t], mm);
        }
    }
    #undef AMPK
    #undef ACC3

    const float n2 = sum0 + sum3 + p1m + r1m + p2m + r2m;
    const float inv2 = __frcp_rn(n2);
    const float invsq = inv2 * inv2;

    // ---- entropy from closed-form sector eigenvalues ----
    float s0 = sum0 * inv2, s3 = sum3 * inv2;
    float p1 = p1m * inv2, r1 = r1m * inv2;
    float c1s = fmaf(c1r, c1r, c1i * c1i) * invsq;
    float t1 = p1 - r1;
    float d1 = sqrtf(fmaf(t1, t1, 4.f * c1s));
    float l1a = 0.5f * ((p1 + r1) + d1);
    float l1b = 0.5f * ((p1 + r1) - d1);
    float p2 = p2m * inv2, r2 = r2m * inv2;
    float c2s = fmaf(c2r, c2r, c2i * c2i) * invsq;
    float t2 = p2 - r2;
    float d2 = sqrtf(fmaf(t2, t2, 4.f * c2s));
    float l2a = 0.5f * ((p2 + r2) + d2);
    float l2b = 0.5f * ((p2 + r2) - d2);
    float e = ent_term(s0) + ent_term(l1a) + ent_term(l1b)
            + ent_term(l2a) + ent_term(l2b) + ent_term(s3)
            + 1.1052408e-10f;   // 4 zero-eigs clipped to 1e-12 in the reference

    // ---- layer 3 epilogue (prescaled tanh) + layer 4 (16->2) ----
    float o0 = s.b4[0], o1 = s.b4[1];
    #pragma unroll
    for (int j = 0; j < 16; j++) {
        float g = tanh_pre(fmaf(inv2, acc[j], s.b3[j]));
        float2 w = *reinterpret_cast<const float2*>(s.W4[j]);
        o0 = fmaf(g, w.x, o0);
        o1 = fmaf(g, w.y, o1);
    }

    out[b]     = x.x * (1.0f - x.x) * o0;
    out[n + b] = o1;

    // ---- deterministic entropy partial sum + fused final mean ----
    #pragma unroll
    for (int o = 16; o > 0; o >>= 1) e += __shfl_xor_sync(0xffffffffu, e, o);
    if ((tid & 31) == 0) red[tid >> 5] = e;
    __syncthreads();
    if (tid == 0) {
        float ssum = 0.f;
        #pragma unroll
        for (int i = 0; i < NTH / 32; i++) ssum += red[i];
        g_partial[blockIdx.x] = ssum;
        __threadfence();
        unsigned old = atomicAdd(&g_count, 1u);
        s_last = (old == gridDim.x - 1);
    }
    __syncthreads();
    if (s_last) {
        const int nblk = gridDim.x;
        float v = 0.f;
        for (int i = tid; i < nblk; i += NTH) v += g_partial[i];
        #pragma unroll
        for (int o = 16; o > 0; o >>= 1) v += __shfl_xor_sync(0xffffffffu, v, o);
        if ((tid & 31) == 0) red[tid >> 5] = v;
        __syncthreads();
        if (tid == 0) {
            float sum = 0.f;
            #pragma unroll
            for (int i = 0; i < NTH / 32; i++) sum += red[i];
            out[2 * n] = sum / (float)n;
            g_count = 0;   // reset for next graph replay
        }
    }
}

extern "C" void kernel_launch(void* const* d_in, const int* in_sizes, int n_in,
                              void* d_out, int out_size)
{
    const float* xt = (const float*)d_in[0];
    const float* W1 = (const float*)d_in[1];
    const float* b1 = (const float*)d_in[2];
    const float* W2 = (const float*)d_in[3];
    const float* b2 = (const float*)d_in[4];
    const float* Wr = (const float*)d_in[5];
    const float* br = (const float*)d_in[6];
    const float* Wi = (const float*)d_in[7];
    const float* bi = (const float*)d_in[8];
    const float* W3 = (const float*)d_in[9];
    const float* b3 = (const float*)d_in[10];
    const float* W4 = (const float*)d_in[11];
    const float* b4 = (const float*)d_in[12];
    // d_in[13] = state_map: fixed 3-photon/4-mode basis, structure hardcoded

    const int n    = in_sizes[0] / 2;
    const int nblk = n / NTH;   // 1024 blocks -> near-perfect wave balance

    float* out = (float*)d_out;
    qpinn_fused<<<nblk, NTH>>>(xt, W1, b1, W2, b2, Wr, br, Wi, bi,
                               W3, b3, W4, b4, out, n);
}